// round 4
// baseline (speedup 1.0000x reference)
#include <cuda_runtime.h>
#include <math.h>

#define B_ 16
#define L_ 2048
#define D_ 768
#define K_ 32
#define NEGINF (-1e30f)
#define TB_ 192   // kernel B block size: 192 threads x float4 = 768 columns

// scratch for per-token scores (allowed: __device__ global, no allocation)
__device__ float g_scores[B_ * L_];

// ---------------------------------------------------------------------------
// Kernel A: scores[b,l] = dot(token_hidden[b,l,:], w_pool) + b_pool
// one warp per token, float4 loads
// ---------------------------------------------------------------------------
__global__ void score_kernel(const float* __restrict__ hid,
                             const float* __restrict__ w,
                             const float* __restrict__ bias) {
    int warp_in_block = threadIdx.x >> 5;
    int lane = threadIdx.x & 31;
    int token = blockIdx.x * (blockDim.x >> 5) + warp_in_block;  // 0 .. B*L-1
    if (token >= B_ * L_) return;

    const float4* row = reinterpret_cast<const float4*>(hid + (size_t)token * D_);
    const float4* w4  = reinterpret_cast<const float4*>(w);

    float acc = 0.0f;
    #pragma unroll
    for (int i = 0; i < D_ / 4 / 32; i++) {   // 192 float4 / 32 lanes = 6
        float4 h = row[lane + i * 32];
        float4 ww = w4[lane + i * 32];
        acc += h.x * ww.x + h.y * ww.y + h.z * ww.z + h.w * ww.w;
    }
    // warp reduce
    #pragma unroll
    for (int off = 16; off > 0; off >>= 1)
        acc += __shfl_xor_sync(0xFFFFFFFFu, acc, off);

    if (lane == 0) g_scores[token] = acc + bias[0];
}

// ---------------------------------------------------------------------------
// Kernel B: one block per (b,k) span. masked softmax over span, then
// H[b,k,:] = sum_l w_l * hid[b,l,:]
// 192 threads; each thread owns one float4 column chunk (LDG.128 path).
// ---------------------------------------------------------------------------
__global__ __launch_bounds__(TB_)
void span_pool_kernel(const float* __restrict__ hid,
                      const float* __restrict__ amask,
                      const int* __restrict__ starts,
                      const int* __restrict__ ends,
                      float* __restrict__ out) {  // out: H then sent_mask
    const int k = blockIdx.x;
    const int b = blockIdx.y;
    const int tid = threadIdx.x;

    __shared__ float wsh[L_];          // exp weights, span-local (8 KB)
    __shared__ float red[6];           // cross-warp reduction (6 warps)
    __shared__ float bcast;

    const int s = starts[b * K_ + k];
    const int e = ends[b * K_ + k];
    const int len = e - s;

    const float* sc = g_scores + b * L_;
    const float* am = amask + b * L_;

    // ---- phase 1: masked max over span ----
    float m = NEGINF;
    for (int i = tid; i < len; i += TB_) {
        int l = s + i;
        if (am[l] >= 0.5f) m = fmaxf(m, sc[l]);
    }
    {
        #pragma unroll
        for (int off = 16; off > 0; off >>= 1)
            m = fmaxf(m, __shfl_xor_sync(0xFFFFFFFFu, m, off));
        if ((tid & 31) == 0) red[tid >> 5] = m;
        __syncthreads();
        if (tid < 32) {
            float v = (tid < 6) ? red[tid] : NEGINF;
            #pragma unroll
            for (int off = 4; off > 0; off >>= 1)
                v = fmaxf(v, __shfl_xor_sync(0xFFFFFFFFu, v, off));
            if (tid == 0) bcast = v;
        }
        __syncthreads();
        m = bcast;
    }

    float4* H4 = reinterpret_cast<float4*>(out + ((size_t)(b * K_ + k)) * D_);
    float* sent_mask = out + (size_t)B_ * K_ * D_;

    if (m <= NEGINF * 0.5f) {
        // empty / fully-masked span: zero row, mask 0
        H4[tid] = make_float4(0.0f, 0.0f, 0.0f, 0.0f);
        if (tid == 0) sent_mask[b * K_ + k] = 0.0f;
        return;
    }

    // ---- phase 2: exp weights + sum ----
    float ssum = 0.0f;
    for (int i = tid; i < len; i += TB_) {
        int l = s + i;
        float v = (am[l] >= 0.5f) ? expf(sc[l] - m) : 0.0f;
        wsh[i] = v;
        ssum += v;
    }
    __syncthreads();  // wsh visible before phase 3
    {
        #pragma unroll
        for (int off = 16; off > 0; off >>= 1)
            ssum += __shfl_xor_sync(0xFFFFFFFFu, ssum, off);
        if ((tid & 31) == 0) red[tid >> 5] = ssum;
        __syncthreads();
        if (tid < 32) {
            float v = (tid < 6) ? red[tid] : 0.0f;
            #pragma unroll
            for (int off = 4; off > 0; off >>= 1)
                v += __shfl_xor_sync(0xFFFFFFFFu, v, off);
            if (tid == 0) bcast = v;
        }
        __syncthreads();
        ssum = bcast;
    }
    const float inv = 1.0f / fmaxf(ssum, 1e-30f);

    // ---- phase 3: weighted accumulate; each thread owns one float4 chunk ----
    const float4* base4 = reinterpret_cast<const float4*>(
        hid + ((size_t)b * L_ + s) * D_);
    const int stride4 = D_ / 4;  // 192 float4 per row

    float4 acc0 = make_float4(0.0f, 0.0f, 0.0f, 0.0f);
    float4 acc1 = make_float4(0.0f, 0.0f, 0.0f, 0.0f);

    int i = 0;
    for (; i + 1 < len; i += 2) {
        float w0 = wsh[i];
        float w1 = wsh[i + 1];
        float4 h0 = base4[(size_t)i * stride4 + tid];
        float4 h1 = base4[(size_t)(i + 1) * stride4 + tid];
        acc0.x += w0 * h0.x; acc0.y += w0 * h0.y;
        acc0.z += w0 * h0.z; acc0.w += w0 * h0.w;
        acc1.x += w1 * h1.x; acc1.y += w1 * h1.y;
        acc1.z += w1 * h1.z; acc1.w += w1 * h1.w;
    }
    if (i < len) {
        float w0 = wsh[i];
        float4 h0 = base4[(size_t)i * stride4 + tid];
        acc0.x += w0 * h0.x; acc0.y += w0 * h0.y;
        acc0.z += w0 * h0.z; acc0.w += w0 * h0.w;
    }

    float4 r;
    r.x = (acc0.x + acc1.x) * inv;
    r.y = (acc0.y + acc1.y) * inv;
    r.z = (acc0.z + acc1.z) * inv;
    r.w = (acc0.w + acc1.w) * inv;
    H4[tid] = r;
    if (tid == 0) sent_mask[b * K_ + k] = 1.0f;
}

// ---------------------------------------------------------------------------
extern "C" void kernel_launch(void* const* d_in, const int* in_sizes, int n_in,
                              void* d_out, int out_size) {
    const float* token_hidden   = (const float*)d_in[0];
    const float* attention_mask = (const float*)d_in[1];
    const int*   span_starts    = (const int*)d_in[2];
    const int*   span_ends      = (const int*)d_in[3];
    const float* w_pool         = (const float*)d_in[4];
    const float* b_pool         = (const float*)d_in[5];
    float* out = (float*)d_out;

    // Kernel A: 8 warps/block, one warp per token
    int tokens = B_ * L_;
    int blocksA = (tokens + 7) / 8;
    score_kernel<<<blocksA, 256>>>(token_hidden, w_pool, b_pool);

    // Kernel B: one block per (b,k)
    dim3 gridB(K_, B_);
    span_pool_kernel<<<gridB, TB_>>>(token_hidden, attention_mask,
                                     span_starts, span_ends, out);
}

// round 6
// speedup vs baseline: 1.6720x; 1.6720x over previous
#include <cuda_runtime.h>
#include <math.h>

#define B_ 16
#define L_ 2048
#define D_ 768
#define K_ 32
#define NEGINF (-1e30f)
#define D4_ (D_ / 4)      // 192 float4 per row
#define CHUNK_ 64         // tokens per B2 block
#define NCHUNK_ (L_ / CHUNK_)  // 32

// scratch (allowed: __device__ globals, no allocation)
__device__ float g_scores[B_ * L_];
__device__ float g_m[B_ * K_];
__device__ float g_inv[B_ * K_];

// ---------------------------------------------------------------------------
// Kernel A: scores[b,l] = dot(token_hidden[b,l,:], w_pool) + b_pool
// one warp per token, float4 loads
// ---------------------------------------------------------------------------
__global__ void score_kernel(const float* __restrict__ hid,
                             const float* __restrict__ w,
                             const float* __restrict__ bias) {
    int warp_in_block = threadIdx.x >> 5;
    int lane = threadIdx.x & 31;
    int token = blockIdx.x * (blockDim.x >> 5) + warp_in_block;
    if (token >= B_ * L_) return;

    const float4* row = reinterpret_cast<const float4*>(hid + (size_t)token * D_);
    const float4* w4  = reinterpret_cast<const float4*>(w);

    float acc = 0.0f;
    #pragma unroll
    for (int i = 0; i < D4_ / 32; i++) {   // 6
        float4 h = row[lane + i * 32];
        float4 ww = w4[lane + i * 32];
        acc += h.x * ww.x + h.y * ww.y + h.z * ww.z + h.w * ww.w;
    }
    #pragma unroll
    for (int off = 16; off > 0; off >>= 1)
        acc += __shfl_xor_sync(0xFFFFFFFFu, acc, off);

    if (lane == 0) g_scores[token] = acc + bias[0];
}

// ---------------------------------------------------------------------------
// Kernel B1: per-span softmax stats (one warp per span) + zero H + sent_mask
// grid: 64 blocks x 256 threads = 512 warps = B*K spans
// ---------------------------------------------------------------------------
__global__ __launch_bounds__(256)
void stats_kernel(const float* __restrict__ amask,
                  const int* __restrict__ starts,
                  const int* __restrict__ ends,
                  float* __restrict__ out) {
    // zero H region [0, B*K*D) with all threads (grid-stride)
    {
        int gtid = blockIdx.x * 256 + threadIdx.x;          // 0..16383
        float4* H4 = reinterpret_cast<float4*>(out);
        const int total4 = B_ * K_ * D4_;                    // 98304
        for (int i = gtid; i < total4; i += 64 * 256)
            H4[i] = make_float4(0.0f, 0.0f, 0.0f, 0.0f);
    }

    int wg = blockIdx.x * 8 + (threadIdx.x >> 5);            // global warp = span id
    int lane = threadIdx.x & 31;
    int b = wg >> 5;
    // span index within batch = wg & 31
    int s = starts[wg];
    int e = ends[wg];

    const float* sc = g_scores + b * L_;
    const float* am = amask + b * L_;

    // pass 1: masked max
    float m = NEGINF;
    for (int l = s + lane; l < e; l += 32)
        if (am[l] >= 0.5f) m = fmaxf(m, sc[l]);
    #pragma unroll
    for (int off = 16; off > 0; off >>= 1)
        m = fmaxf(m, __shfl_xor_sync(0xFFFFFFFFu, m, off));

    // pass 2: exp-sum (skip if no valid token)
    float ssum = 0.0f;
    if (m > NEGINF * 0.5f) {
        for (int l = s + lane; l < e; l += 32)
            if (am[l] >= 0.5f) ssum += expf(sc[l] - m);
        #pragma unroll
        for (int off = 16; off > 0; off >>= 1)
            ssum += __shfl_xor_sync(0xFFFFFFFFu, ssum, off);
    }

    if (lane == 0) {
        g_m[wg] = m;
        g_inv[wg] = (ssum > 0.0f) ? (1.0f / ssum) : 0.0f;
        out[(size_t)B_ * K_ * D_ + wg] = (ssum > 0.0f) ? 1.0f : 0.0f;
    }
}

// ---------------------------------------------------------------------------
// Kernel B2: balanced chunk accumulation. grid = (NCHUNK_, B_), 192 threads.
// Each block owns 64 consecutive tokens; finds each token's span (binary
// search), precomputes normalized weights, then accumulates per-span runs
// with 4-token unroll and flushes via atomicAdd.
// ---------------------------------------------------------------------------
__global__ __launch_bounds__(192)
void accum_kernel(const float* __restrict__ hid,
                  const float* __restrict__ amask,
                  const int* __restrict__ starts,
                  const int* __restrict__ ends,
                  float* __restrict__ out) {
    const int c = blockIdx.x;           // chunk
    const int b = blockIdx.y;           // batch
    const int tid = threadIdx.x;

    __shared__ int   s_start[K_];
    __shared__ int   s_end[K_];
    __shared__ int   sid[CHUNK_];
    __shared__ float wgt[CHUNK_];

    if (tid < K_) {
        s_start[tid] = starts[b * K_ + tid];
        s_end[tid]   = ends[b * K_ + tid];
    }
    __syncthreads();

    const int base = c * CHUNK_;        // first token of chunk
    const float* sc = g_scores + b * L_;
    const float* am = amask + b * L_;

    if (tid < CHUNK_) {
        int l = base + tid;
        // binary search: smallest k with s_end[k] > l
        int lo = 0, hi = K_;
        while (lo < hi) {
            int mid = (lo + hi) >> 1;
            if (s_end[mid] > l) hi = mid; else lo = mid + 1;
        }
        int span = -1;
        float w = 0.0f;
        if (lo < K_ && s_start[lo] <= l) {
            span = lo;
            float inv = g_inv[b * K_ + lo];
            if (inv > 0.0f && am[l] >= 0.5f)
                w = expf(sc[l] - g_m[b * K_ + lo]) * inv;
        }
        sid[tid] = span;
        wgt[tid] = w;
    }
    __syncthreads();

    const float4* hb = reinterpret_cast<const float4*>(
        hid + ((size_t)b * L_ + base) * D_);

    int i = 0;
    while (i < CHUNK_) {
        int span = sid[i];
        int j = i + 1;
        while (j < CHUNK_ && sid[j] == span) j++;
        if (span >= 0) {
            float4 a0 = make_float4(0.f, 0.f, 0.f, 0.f);
            float4 a1 = make_float4(0.f, 0.f, 0.f, 0.f);
            float4 a2 = make_float4(0.f, 0.f, 0.f, 0.f);
            float4 a3 = make_float4(0.f, 0.f, 0.f, 0.f);
            int t = i;
            for (; t + 4 <= j; t += 4) {
                float w0 = wgt[t], w1 = wgt[t + 1], w2 = wgt[t + 2], w3 = wgt[t + 3];
                float4 h0 = hb[(size_t)(t)     * D4_ + tid];
                float4 h1 = hb[(size_t)(t + 1) * D4_ + tid];
                float4 h2 = hb[(size_t)(t + 2) * D4_ + tid];
                float4 h3 = hb[(size_t)(t + 3) * D4_ + tid];
                a0.x += w0 * h0.x; a0.y += w0 * h0.y; a0.z += w0 * h0.z; a0.w += w0 * h0.w;
                a1.x += w1 * h1.x; a1.y += w1 * h1.y; a1.z += w1 * h1.z; a1.w += w1 * h1.w;
                a2.x += w2 * h2.x; a2.y += w2 * h2.y; a2.z += w2 * h2.z; a2.w += w2 * h2.w;
                a3.x += w3 * h3.x; a3.y += w3 * h3.y; a3.z += w3 * h3.z; a3.w += w3 * h3.w;
            }
            for (; t < j; t++) {
                float w0 = wgt[t];
                float4 h0 = hb[(size_t)t * D4_ + tid];
                a0.x += w0 * h0.x; a0.y += w0 * h0.y; a0.z += w0 * h0.z; a0.w += w0 * h0.w;
            }
            float rx = a0.x + a1.x + a2.x + a3.x;
            float ry = a0.y + a1.y + a2.y + a3.y;
            float rz = a0.z + a1.z + a2.z + a3.z;
            float rw = a0.w + a1.w + a2.w + a3.w;
            float* Hrow = out + ((size_t)(b * K_ + span)) * D_ + 4 * tid;
            atomicAdd(Hrow + 0, rx);
            atomicAdd(Hrow + 1, ry);
            atomicAdd(Hrow + 2, rz);
            atomicAdd(Hrow + 3, rw);
        }
        i = j;
    }
}

// ---------------------------------------------------------------------------
extern "C" void kernel_launch(void* const* d_in, const int* in_sizes, int n_in,
                              void* d_out, int out_size) {
    const float* token_hidden   = (const float*)d_in[0];
    const float* attention_mask = (const float*)d_in[1];
    const int*   span_starts    = (const int*)d_in[2];
    const int*   span_ends      = (const int*)d_in[3];
    const float* w_pool         = (const float*)d_in[4];
    const float* b_pool         = (const float*)d_in[5];
    float* out = (float*)d_out;

    // Kernel A: 8 warps/block, one warp per token
    int tokens = B_ * L_;
    int blocksA = (tokens + 7) / 8;
    score_kernel<<<blocksA, 256>>>(token_hidden, w_pool, b_pool);

    // Kernel B1: stats + zero H + sent_mask (512 warps = 512 spans)
    stats_kernel<<<64, 256>>>(attention_mask, span_starts, span_ends, out);

    // Kernel B2: balanced chunk accumulation
    dim3 gridB2(NCHUNK_, B_);
    accum_kernel<<<gridB2, 192>>>(token_hidden, attention_mask,
                                  span_starts, span_ends, out);
}

// round 7
// speedup vs baseline: 1.8661x; 1.1161x over previous
#include <cuda_runtime.h>
#include <math.h>

#define B_ 16
#define L_ 2048
#define D_ 768
#define K_ 32
#define NEGINF (-1e30f)
#define D4_ (D_ / 4)           // 192 float4 per row
#define CHUNK_ 64              // tokens per B2 block
#define NCHUNK_ (L_ / CHUNK_)  // 32

// scratch (allowed: __device__ globals, no allocation)
__device__ float g_scores[B_ * L_];
__device__ float g_m[B_ * K_];
__device__ float g_inv[B_ * K_];

// ---------------------------------------------------------------------------
// Kernel A: scores[b,l] = dot(token_hidden[b,l,:], w_pool) + b_pool
// 4 tokens per warp: w_pool cached in registers, 24 independent LDG.128
// in flight per warp, 4 interleaved butterfly reductions.
// ---------------------------------------------------------------------------
__global__ __launch_bounds__(256)
void score_kernel(const float* __restrict__ hid,
                  const float* __restrict__ w,
                  const float* __restrict__ bias) {
    const int warp_in_block = threadIdx.x >> 5;
    const int lane = threadIdx.x & 31;
    const int warp_g = blockIdx.x * 8 + warp_in_block;
    const int token_base = warp_g * 4;           // 4 tokens per warp
    if (token_base >= B_ * L_) return;

    const float4* w4 = reinterpret_cast<const float4*>(w);

    // preload w_pool slice for this lane (6 float4 = 24 regs), reused 4x
    float4 ww[6];
    #pragma unroll
    for (int i = 0; i < 6; i++) ww[i] = w4[lane + i * 32];

    float acc[4] = {0.0f, 0.0f, 0.0f, 0.0f};
    #pragma unroll
    for (int t = 0; t < 4; t++) {
        const float4* row = reinterpret_cast<const float4*>(
            hid + (size_t)(token_base + t) * D_);
        #pragma unroll
        for (int i = 0; i < 6; i++) {
            float4 h = row[lane + i * 32];
            acc[t] += h.x * ww[i].x + h.y * ww[i].y
                    + h.z * ww[i].z + h.w * ww[i].w;
        }
    }

    // 4 interleaved butterfly reductions (chains pipeline across t)
    #pragma unroll
    for (int off = 16; off > 0; off >>= 1) {
        #pragma unroll
        for (int t = 0; t < 4; t++)
            acc[t] += __shfl_xor_sync(0xFFFFFFFFu, acc[t], off);
    }

    if (lane < 4) g_scores[token_base + lane] = acc[lane] + bias[0];
}

// ---------------------------------------------------------------------------
// Kernel B1: per-span softmax stats (one warp per span) + zero H + sent_mask
// grid: 64 blocks x 256 threads = 512 warps = B*K spans
// ---------------------------------------------------------------------------
__global__ __launch_bounds__(256)
void stats_kernel(const float* __restrict__ amask,
                  const int* __restrict__ starts,
                  const int* __restrict__ ends,
                  float* __restrict__ out) {
    // zero H region [0, B*K*D) with all threads (grid-stride)
    {
        int gtid = blockIdx.x * 256 + threadIdx.x;          // 0..16383
        float4* H4 = reinterpret_cast<float4*>(out);
        const int total4 = B_ * K_ * D4_;                    // 98304
        for (int i = gtid; i < total4; i += 64 * 256)
            H4[i] = make_float4(0.0f, 0.0f, 0.0f, 0.0f);
    }

    int wg = blockIdx.x * 8 + (threadIdx.x >> 5);            // span id
    int lane = threadIdx.x & 31;
    int b = wg >> 5;
    int s = starts[wg];
    int e = ends[wg];

    const float* sc = g_scores + b * L_;
    const float* am = amask + b * L_;

    // pass 1: masked max
    float m = NEGINF;
    for (int l = s + lane; l < e; l += 32)
        if (am[l] >= 0.5f) m = fmaxf(m, sc[l]);
    #pragma unroll
    for (int off = 16; off > 0; off >>= 1)
        m = fmaxf(m, __shfl_xor_sync(0xFFFFFFFFu, m, off));

    // pass 2: exp-sum (skip if no valid token)
    float ssum = 0.0f;
    if (m > NEGINF * 0.5f) {
        for (int l = s + lane; l < e; l += 32)
            if (am[l] >= 0.5f) ssum += expf(sc[l] - m);
        #pragma unroll
        for (int off = 16; off > 0; off >>= 1)
            ssum += __shfl_xor_sync(0xFFFFFFFFu, ssum, off);
    }

    if (lane == 0) {
        g_m[wg] = m;
        g_inv[wg] = (ssum > 0.0f) ? (1.0f / ssum) : 0.0f;
        out[(size_t)B_ * K_ * D_ + wg] = (ssum > 0.0f) ? 1.0f : 0.0f;
    }
}

// ---------------------------------------------------------------------------
// Kernel B2: balanced chunk accumulation. grid = (NCHUNK_, B_), 192 threads.
// Each block owns 64 consecutive tokens; per-token span found via binary
// search, weights pre-normalized; same-span runs accumulated with 8-token
// unroll (8 LDG.128 in flight / thread) and flushed via atomicAdd.
// ---------------------------------------------------------------------------
__global__ __launch_bounds__(192)
void accum_kernel(const float* __restrict__ hid,
                  const float* __restrict__ amask,
                  const int* __restrict__ starts,
                  const int* __restrict__ ends,
                  float* __restrict__ out) {
    const int c = blockIdx.x;           // chunk
    const int b = blockIdx.y;           // batch
    const int tid = threadIdx.x;

    __shared__ int   s_start[K_];
    __shared__ int   s_end[K_];
    __shared__ int   sid[CHUNK_];
    __shared__ float wgt[CHUNK_];

    if (tid < K_) {
        s_start[tid] = starts[b * K_ + tid];
        s_end[tid]   = ends[b * K_ + tid];
    }
    __syncthreads();

    const int base = c * CHUNK_;        // first token of chunk
    const float* sc = g_scores + b * L_;
    const float* am = amask + b * L_;

    if (tid < CHUNK_) {
        int l = base + tid;
        // binary search: smallest k with s_end[k] > l
        int lo = 0, hi = K_;
        while (lo < hi) {
            int mid = (lo + hi) >> 1;
            if (s_end[mid] > l) hi = mid; else lo = mid + 1;
        }
        int span = -1;
        float w = 0.0f;
        if (lo < K_ && s_start[lo] <= l) {
            span = lo;
            float inv = g_inv[b * K_ + lo];
            if (inv > 0.0f && am[l] >= 0.5f)
                w = expf(sc[l] - g_m[b * K_ + lo]) * inv;
        }
        sid[tid] = span;
        wgt[tid] = w;
    }
    __syncthreads();

    const float4* hb = reinterpret_cast<const float4*>(
        hid + ((size_t)b * L_ + base) * D_);

    int i = 0;
    while (i < CHUNK_) {
        int span = sid[i];
        int j = i + 1;
        while (j < CHUNK_ && sid[j] == span) j++;
        if (span >= 0) {
            float4 a0 = make_float4(0.f, 0.f, 0.f, 0.f);
            float4 a1 = make_float4(0.f, 0.f, 0.f, 0.f);
            float4 a2 = make_float4(0.f, 0.f, 0.f, 0.f);
            float4 a3 = make_float4(0.f, 0.f, 0.f, 0.f);
            int t = i;
            for (; t + 8 <= j; t += 8) {
                float w0 = wgt[t],     w1 = wgt[t + 1], w2 = wgt[t + 2], w3 = wgt[t + 3];
                float w4 = wgt[t + 4], w5 = wgt[t + 5], w6 = wgt[t + 6], w7 = wgt[t + 7];
                float4 h0 = hb[(size_t)(t)     * D4_ + tid];
                float4 h1 = hb[(size_t)(t + 1) * D4_ + tid];
                float4 h2 = hb[(size_t)(t + 2) * D4_ + tid];
                float4 h3 = hb[(size_t)(t + 3) * D4_ + tid];
                float4 h4 = hb[(size_t)(t + 4) * D4_ + tid];
                float4 h5 = hb[(size_t)(t + 5) * D4_ + tid];
                float4 h6 = hb[(size_t)(t + 6) * D4_ + tid];
                float4 h7 = hb[(size_t)(t + 7) * D4_ + tid];
                a0.x += w0 * h0.x; a0.y += w0 * h0.y; a0.z += w0 * h0.z; a0.w += w0 * h0.w;
                a1.x += w1 * h1.x; a1.y += w1 * h1.y; a1.z += w1 * h1.z; a1.w += w1 * h1.w;
                a2.x += w2 * h2.x; a2.y += w2 * h2.y; a2.z += w2 * h2.z; a2.w += w2 * h2.w;
                a3.x += w3 * h3.x; a3.y += w3 * h3.y; a3.z += w3 * h3.z; a3.w += w3 * h3.w;
                a0.x += w4 * h4.x; a0.y += w4 * h4.y; a0.z += w4 * h4.z; a0.w += w4 * h4.w;
                a1.x += w5 * h5.x; a1.y += w5 * h5.y; a1.z += w5 * h5.z; a1.w += w5 * h5.w;
                a2.x += w6 * h6.x; a2.y += w6 * h6.y; a2.z += w6 * h6.z; a2.w += w6 * h6.w;
                a3.x += w7 * h7.x; a3.y += w7 * h7.y; a3.z += w7 * h7.z; a3.w += w7 * h7.w;
            }
            for (; t + 4 <= j; t += 4) {
                float w0 = wgt[t], w1 = wgt[t + 1], w2 = wgt[t + 2], w3 = wgt[t + 3];
                float4 h0 = hb[(size_t)(t)     * D4_ + tid];
                float4 h1 = hb[(size_t)(t + 1) * D4_ + tid];
                float4 h2 = hb[(size_t)(t + 2) * D4_ + tid];
                float4 h3 = hb[(size_t)(t + 3) * D4_ + tid];
                a0.x += w0 * h0.x; a0.y += w0 * h0.y; a0.z += w0 * h0.z; a0.w += w0 * h0.w;
                a1.x += w1 * h1.x; a1.y += w1 * h1.y; a1.z += w1 * h1.z; a1.w += w1 * h1.w;
                a2.x += w2 * h2.x; a2.y += w2 * h2.y; a2.z += w2 * h2.z; a2.w += w2 * h2.w;
                a3.x += w3 * h3.x; a3.y += w3 * h3.y; a3.z += w3 * h3.z; a3.w += w3 * h3.w;
            }
            for (; t < j; t++) {
                float w0 = wgt[t];
                float4 h0 = hb[(size_t)t * D4_ + tid];
                a0.x += w0 * h0.x; a0.y += w0 * h0.y; a0.z += w0 * h0.z; a0.w += w0 * h0.w;
            }
            float rx = a0.x + a1.x + a2.x + a3.x;
            float ry = a0.y + a1.y + a2.y + a3.y;
            float rz = a0.z + a1.z + a2.z + a3.z;
            float rw = a0.w + a1.w + a2.w + a3.w;
            float* Hrow = out + ((size_t)(b * K_ + span)) * D_ + 4 * tid;
            atomicAdd(Hrow + 0, rx);
            atomicAdd(Hrow + 1, ry);
            atomicAdd(Hrow + 2, rz);
            atomicAdd(Hrow + 3, rw);
        }
        i = j;
    }
}

// ---------------------------------------------------------------------------
extern "C" void kernel_launch(void* const* d_in, const int* in_sizes, int n_in,
                              void* d_out, int out_size) {
    const float* token_hidden   = (const float*)d_in[0];
    const float* attention_mask = (const float*)d_in[1];
    const int*   span_starts    = (const int*)d_in[2];
    const int*   span_ends      = (const int*)d_in[3];
    const float* w_pool         = (const float*)d_in[4];
    const float* b_pool         = (const float*)d_in[5];
    float* out = (float*)d_out;

    // Kernel A: 8 warps/block, 4 tokens/warp -> 32 tokens/block
    int tokens = B_ * L_;               // 32768
    int blocksA = tokens / 32;          // 1024
    score_kernel<<<blocksA, 256>>>(token_hidden, w_pool, b_pool);

    // Kernel B1: stats + zero H + sent_mask (512 warps = 512 spans)
    stats_kernel<<<64, 256>>>(attention_mask, span_starts, span_ends, out);

    // Kernel B2: balanced chunk accumulation
    dim3 gridB2(NCHUNK_, B_);
    accum_kernel<<<gridB2, 192>>>(token_hidden, attention_mask,
                                  span_starts, span_ends, out);
}

// round 8
// speedup vs baseline: 2.0674x; 1.1079x over previous
#include <cuda_runtime.h>
#include <math.h>

#define B_ 16
#define L_ 2048
#define D_ 768
#define K_ 32
#define NEGINF (-1e30f)
#define D4_ (D_ / 4)           // 192 float4 per row
#define CHUNK_ 32              // tokens per B2 block
#define NCHUNK_ (L_ / CHUNK_)  // 64

// scratch (allowed: __device__ globals, no allocation)
__device__ float g_scores[B_ * L_];
__device__ float g_m[B_ * K_];
__device__ float g_inv[B_ * K_];

// ---------------------------------------------------------------------------
// Kernel A: scores[b,l] = dot(token_hidden[b,l,:], w_pool) + b_pool
// 2 tokens per warp, w_pool in shared (saves 24 regs -> higher occupancy),
// 12 independent LDG.128 in flight per warp. Tokens outside the covered
// span range [starts[b,0], ends[b,K-1]) are skipped entirely.
// ---------------------------------------------------------------------------
__global__ __launch_bounds__(256)
void score_kernel(const float* __restrict__ hid,
                  const float* __restrict__ w,
                  const float* __restrict__ bias,
                  const int* __restrict__ starts,
                  const int* __restrict__ ends) {
    __shared__ float4 wsh[D4_];        // 3 KB
    if (threadIdx.x < D4_)
        wsh[threadIdx.x] = reinterpret_cast<const float4*>(w)[threadIdx.x];
    __syncthreads();

    const int lane = threadIdx.x & 31;
    const int warp_g = blockIdx.x * 8 + (threadIdx.x >> 5);
    const int token0 = warp_g * 2;               // 2 tokens per warp
    const int b = token0 >> 11;                  // / L_
    const int l0 = token0 & (L_ - 1);

    // coverage skip: scores only needed for l in [s0, eK)
    const int s0 = starts[b * K_];
    const int eK = ends[b * K_ + K_ - 1];
    if (l0 + 1 < s0 || l0 >= eK) return;

    const float4* r0 = reinterpret_cast<const float4*>(hid + (size_t)token0 * D_);
    const float4* r1 = r0 + D4_;

    float acc[2] = {0.0f, 0.0f};
    #pragma unroll
    for (int i = 0; i < 6; i++) {
        float4 h0 = r0[lane + i * 32];
        float4 h1 = r1[lane + i * 32];
        float4 ww = wsh[lane + i * 32];
        acc[0] += h0.x * ww.x + h0.y * ww.y + h0.z * ww.z + h0.w * ww.w;
        acc[1] += h1.x * ww.x + h1.y * ww.y + h1.z * ww.z + h1.w * ww.w;
    }

    #pragma unroll
    for (int off = 16; off > 0; off >>= 1) {
        acc[0] += __shfl_xor_sync(0xFFFFFFFFu, acc[0], off);
        acc[1] += __shfl_xor_sync(0xFFFFFFFFu, acc[1], off);
    }

    if (lane < 2) g_scores[token0 + lane] = acc[lane] + bias[0];
}

// ---------------------------------------------------------------------------
// Kernel B1: per-span softmax stats (one warp per span) + zero H + sent_mask
// grid: 64 blocks x 256 threads = 512 warps = B*K spans
// ---------------------------------------------------------------------------
__global__ __launch_bounds__(256)
void stats_kernel(const float* __restrict__ amask,
                  const int* __restrict__ starts,
                  const int* __restrict__ ends,
                  float* __restrict__ out) {
    // zero H region [0, B*K*D) with all threads (grid-stride)
    {
        int gtid = blockIdx.x * 256 + threadIdx.x;
        float4* H4 = reinterpret_cast<float4*>(out);
        const int total4 = B_ * K_ * D4_;                    // 98304
        for (int i = gtid; i < total4; i += 64 * 256)
            H4[i] = make_float4(0.0f, 0.0f, 0.0f, 0.0f);
    }

    int wg = blockIdx.x * 8 + (threadIdx.x >> 5);            // span id
    int lane = threadIdx.x & 31;
    int b = wg >> 5;
    int s = starts[wg];
    int e = ends[wg];

    const float* sc = g_scores + b * L_;
    const float* am = amask + b * L_;

    // pass 1: masked max
    float m = NEGINF;
    for (int l = s + lane; l < e; l += 32)
        if (am[l] >= 0.5f) m = fmaxf(m, sc[l]);
    #pragma unroll
    for (int off = 16; off > 0; off >>= 1)
        m = fmaxf(m, __shfl_xor_sync(0xFFFFFFFFu, m, off));

    // pass 2: exp-sum (skip if no valid token)
    float ssum = 0.0f;
    if (m > NEGINF * 0.5f) {
        for (int l = s + lane; l < e; l += 32)
            if (am[l] >= 0.5f) ssum += expf(sc[l] - m);
        #pragma unroll
        for (int off = 16; off > 0; off >>= 1)
            ssum += __shfl_xor_sync(0xFFFFFFFFu, ssum, off);
    }

    if (lane == 0) {
        g_m[wg] = m;
        g_inv[wg] = (ssum > 0.0f) ? (1.0f / ssum) : 0.0f;
        out[(size_t)B_ * K_ * D_ + wg] = (ssum > 0.0f) ? 1.0f : 0.0f;
    }
}

// ---------------------------------------------------------------------------
// Kernel B2: balanced chunk accumulation. grid = (NCHUNK_, B_) = 1024 blocks,
// 192 threads. Each block owns 32 consecutive tokens; per-token span via
// binary search, weights pre-normalized; same-span runs accumulated with
// 8-token unroll and flushed via atomicAdd.
// ---------------------------------------------------------------------------
__global__ __launch_bounds__(192)
void accum_kernel(const float* __restrict__ hid,
                  const float* __restrict__ amask,
                  const int* __restrict__ starts,
                  const int* __restrict__ ends,
                  float* __restrict__ out) {
    const int c = blockIdx.x;           // chunk
    const int b = blockIdx.y;           // batch
    const int tid = threadIdx.x;

    __shared__ int   s_start[K_];
    __shared__ int   s_end[K_];
    __shared__ int   sid[CHUNK_];
    __shared__ float wgt[CHUNK_];

    if (tid < K_) {
        s_start[tid] = starts[b * K_ + tid];
        s_end[tid]   = ends[b * K_ + tid];
    }
    __syncthreads();

    const int base = c * CHUNK_;        // first token of chunk
    const float* sc = g_scores + b * L_;
    const float* am = amask + b * L_;

    if (tid < CHUNK_) {
        int l = base + tid;
        // binary search: smallest k with s_end[k] > l
        int lo = 0, hi = K_;
        while (lo < hi) {
            int mid = (lo + hi) >> 1;
            if (s_end[mid] > l) hi = mid; else lo = mid + 1;
        }
        int span = -1;
        float w = 0.0f;
        if (lo < K_ && s_start[lo] <= l) {
            span = lo;
            float inv = g_inv[b * K_ + lo];
            if (inv > 0.0f && am[l] >= 0.5f)
                w = expf(sc[l] - g_m[b * K_ + lo]) * inv;
        }
        sid[tid] = span;
        wgt[tid] = w;
    }
    __syncthreads();

    const float4* hb = reinterpret_cast<const float4*>(
        hid + ((size_t)b * L_ + base) * D_);

    int i = 0;
    while (i < CHUNK_) {
        int span = sid[i];
        int j = i + 1;
        while (j < CHUNK_ && sid[j] == span) j++;
        if (span >= 0) {
            float4 a0 = make_float4(0.f, 0.f, 0.f, 0.f);
            float4 a1 = make_float4(0.f, 0.f, 0.f, 0.f);
            float4 a2 = make_float4(0.f, 0.f, 0.f, 0.f);
            float4 a3 = make_float4(0.f, 0.f, 0.f, 0.f);
            int t = i;
            for (; t + 8 <= j; t += 8) {
                float w0 = wgt[t],     w1 = wgt[t + 1], w2 = wgt[t + 2], w3 = wgt[t + 3];
                float w4 = wgt[t + 4], w5 = wgt[t + 5], w6 = wgt[t + 6], w7 = wgt[t + 7];
                float4 h0 = hb[(size_t)(t)     * D4_ + tid];
                float4 h1 = hb[(size_t)(t + 1) * D4_ + tid];
                float4 h2 = hb[(size_t)(t + 2) * D4_ + tid];
                float4 h3 = hb[(size_t)(t + 3) * D4_ + tid];
                float4 h4 = hb[(size_t)(t + 4) * D4_ + tid];
                float4 h5 = hb[(size_t)(t + 5) * D4_ + tid];
                float4 h6 = hb[(size_t)(t + 6) * D4_ + tid];
                float4 h7 = hb[(size_t)(t + 7) * D4_ + tid];
                a0.x += w0 * h0.x; a0.y += w0 * h0.y; a0.z += w0 * h0.z; a0.w += w0 * h0.w;
                a1.x += w1 * h1.x; a1.y += w1 * h1.y; a1.z += w1 * h1.z; a1.w += w1 * h1.w;
                a2.x += w2 * h2.x; a2.y += w2 * h2.y; a2.z += w2 * h2.z; a2.w += w2 * h2.w;
                a3.x += w3 * h3.x; a3.y += w3 * h3.y; a3.z += w3 * h3.z; a3.w += w3 * h3.w;
                a0.x += w4 * h4.x; a0.y += w4 * h4.y; a0.z += w4 * h4.z; a0.w += w4 * h4.w;
                a1.x += w5 * h5.x; a1.y += w5 * h5.y; a1.z += w5 * h5.z; a1.w += w5 * h5.w;
                a2.x += w6 * h6.x; a2.y += w6 * h6.y; a2.z += w6 * h6.z; a2.w += w6 * h6.w;
                a3.x += w7 * h7.x; a3.y += w7 * h7.y; a3.z += w7 * h7.z; a3.w += w7 * h7.w;
            }
            for (; t + 4 <= j; t += 4) {
                float w0 = wgt[t], w1 = wgt[t + 1], w2 = wgt[t + 2], w3 = wgt[t + 3];
                float4 h0 = hb[(size_t)(t)     * D4_ + tid];
                float4 h1 = hb[(size_t)(t + 1) * D4_ + tid];
                float4 h2 = hb[(size_t)(t + 2) * D4_ + tid];
                float4 h3 = hb[(size_t)(t + 3) * D4_ + tid];
                a0.x += w0 * h0.x; a0.y += w0 * h0.y; a0.z += w0 * h0.z; a0.w += w0 * h0.w;
                a1.x += w1 * h1.x; a1.y += w1 * h1.y; a1.z += w1 * h1.z; a1.w += w1 * h1.w;
                a2.x += w2 * h2.x; a2.y += w2 * h2.y; a2.z += w2 * h2.z; a2.w += w2 * h2.w;
                a3.x += w3 * h3.x; a3.y += w3 * h3.y; a3.z += w3 * h3.z; a3.w += w3 * h3.w;
            }
            for (; t < j; t++) {
                float w0 = wgt[t];
                float4 h0 = hb[(size_t)t * D4_ + tid];
                a0.x += w0 * h0.x; a0.y += w0 * h0.y; a0.z += w0 * h0.z; a0.w += w0 * h0.w;
            }
            float rx = a0.x + a1.x + a2.x + a3.x;
            float ry = a0.y + a1.y + a2.y + a3.y;
            float rz = a0.z + a1.z + a2.z + a3.z;
            float rw = a0.w + a1.w + a2.w + a3.w;
            float* Hrow = out + ((size_t)(b * K_ + span)) * D_ + 4 * tid;
            atomicAdd(Hrow + 0, rx);
            atomicAdd(Hrow + 1, ry);
            atomicAdd(Hrow + 2, rz);
            atomicAdd(Hrow + 3, rw);
        }
        i = j;
    }
}

// ---------------------------------------------------------------------------
extern "C" void kernel_launch(void* const* d_in, const int* in_sizes, int n_in,
                              void* d_out, int out_size) {
    const float* token_hidden   = (const float*)d_in[0];
    const float* attention_mask = (const float*)d_in[1];
    const int*   span_starts    = (const int*)d_in[2];
    const int*   span_ends      = (const int*)d_in[3];
    const float* w_pool         = (const float*)d_in[4];
    const float* b_pool         = (const float*)d_in[5];
    float* out = (float*)d_out;

    // Kernel A: 8 warps/block, 2 tokens/warp -> 16 tokens/block
    int tokens = B_ * L_;               // 32768
    int blocksA = tokens / 16;          // 2048
    score_kernel<<<blocksA, 256>>>(token_hidden, w_pool, b_pool,
                                   span_starts, span_ends);

    // Kernel B1: stats + zero H + sent_mask (512 warps = 512 spans)
    stats_kernel<<<64, 256>>>(attention_mask, span_starts, span_ends, out);

    // Kernel B2: balanced chunk accumulation (1024 blocks)
    dim3 gridB2(NCHUNK_, B_);
    accum_kernel<<<gridB2, 192>>>(token_hidden, attention_mask,
                                  span_starts, span_ends, out);
}

// round 10
// speedup vs baseline: 2.3725x; 1.1476x over previous
#include <cuda_runtime.h>
#include <math.h>

#define B_ 16
#define L_ 2048
#define D_ 768
#define K_ 32
#define D4_ (D_ / 4)           // 192 float4 per row
#define CHUNK_ 32              // tokens per fused block
#define NCHUNK_ (L_ / CHUNK_)  // 64

// scratch (allowed: __device__ global, no allocation)
__device__ float g_denom[B_ * K_];

// ---------------------------------------------------------------------------
// Kernel 0: zero the H region of out and g_denom (out is poisoned; atomics
// need clean accumulators every call).
// ---------------------------------------------------------------------------
__global__ __launch_bounds__(256)
void zero_kernel(float* __restrict__ out) {
    int gtid = blockIdx.x * 256 + threadIdx.x;
    float4* H4 = reinterpret_cast<float4*>(out);
    const int total4 = B_ * K_ * D4_;                 // 98304
    for (int i = gtid; i < total4; i += 96 * 256)
        H4[i] = make_float4(0.0f, 0.0f, 0.0f, 0.0f);
    if (gtid < B_ * K_) g_denom[gtid] = 0.0f;
}

// ---------------------------------------------------------------------------
// Fused kernel: one DRAM read of token_hidden.
// grid = (NCHUNK_, B_) = 1024 blocks, 192 threads.
// Phase 0: span id per token (binary search, smem tables).
// Phase 1: warp-per-token dot with w_pool (smem) -> wgt[t] = exp(score),
//          token atomicAdd into g_denom[span]. Rows enter L1/L2 here.
// Phase 2: run-wise 8-unroll accumulate of wgt[t]*row (re-read hits L1/L2),
//          atomicAdd unnormalized sums into out.
// ---------------------------------------------------------------------------
__global__ __launch_bounds__(192)
void fused_kernel(const float* __restrict__ hid,
                  const float* __restrict__ amask,
                  const int* __restrict__ starts,
                  const int* __restrict__ ends,
                  const float* __restrict__ w,
                  const float* __restrict__ bias,
                  float* __restrict__ out) {
    const int c = blockIdx.x;           // chunk
    const int b = blockIdx.y;           // batch
    const int tid = threadIdx.x;
    const int wid = tid >> 5;           // 0..5
    const int lane = tid & 31;

    __shared__ float4 wsh[D4_];         // 3 KB, D4_ == 192 == blockDim
    __shared__ int   s_start[K_];
    __shared__ int   s_end[K_];
    __shared__ int   sid[CHUNK_];
    __shared__ float wgt[CHUNK_];

    wsh[tid] = reinterpret_cast<const float4*>(w)[tid];
    if (tid < K_) {
        s_start[tid] = starts[b * K_ + tid];
        s_end[tid]   = ends[b * K_ + tid];
    }
    __syncthreads();

    const int base = c * CHUNK_;
    const float* am = amask + b * L_;
    const float4* hb = reinterpret_cast<const float4*>(
        hid + ((size_t)b * L_ + base) * D_);

    // ---- phase 0: span id per token ----
    if (tid < CHUNK_) {
        int l = base + tid;
        int lo = 0, hi = K_;
        while (lo < hi) {
            int mid = (lo + hi) >> 1;
            if (s_end[mid] > l) hi = mid; else lo = mid + 1;
        }
        sid[tid] = (lo < K_ && s_start[lo] <= l) ? lo : -1;
    }
    __syncthreads();

    // ---- phase 1: scores + exp weights + denom atomics ----
    const float bias0 = bias[0];
    for (int t = wid; t < CHUNK_; t += 6) {
        int span = sid[t];
        if (span < 0) { if (lane == 0) wgt[t] = 0.0f; continue; }
        const float4* row = hb + (size_t)t * D4_;
        float acc = 0.0f;
        #pragma unroll
        for (int i = 0; i < 6; i++) {
            float4 h = row[lane + i * 32];
            float4 ww = wsh[lane + i * 32];
            acc += h.x * ww.x + h.y * ww.y + h.z * ww.z + h.w * ww.w;
        }
        #pragma unroll
        for (int off = 16; off > 0; off >>= 1)
            acc += __shfl_xor_sync(0xFFFFFFFFu, acc, off);
        if (lane == 0) {
            float e = (am[base + t] >= 0.5f) ? expf(acc + bias0) : 0.0f;
            wgt[t] = e;
            if (e > 0.0f) atomicAdd(&g_denom[b * K_ + span], e);
        }
    }
    __syncthreads();

    // ---- phase 2: run-wise unnormalized accumulation ----
    int i = 0;
    while (i < CHUNK_) {
        int span = sid[i];
        int j = i + 1;
        while (j < CHUNK_ && sid[j] == span) j++;
        if (span >= 0) {
            float4 a0 = make_float4(0.f, 0.f, 0.f, 0.f);
            float4 a1 = make_float4(0.f, 0.f, 0.f, 0.f);
            float4 a2 = make_float4(0.f, 0.f, 0.f, 0.f);
            float4 a3 = make_float4(0.f, 0.f, 0.f, 0.f);
            int t = i;
            for (; t + 8 <= j; t += 8) {
                float w0 = wgt[t],     w1 = wgt[t + 1], w2 = wgt[t + 2], w3 = wgt[t + 3];
                float w4 = wgt[t + 4], w5 = wgt[t + 5], w6 = wgt[t + 6], w7 = wgt[t + 7];
                float4 h0 = hb[(size_t)(t)     * D4_ + tid];
                float4 h1 = hb[(size_t)(t + 1) * D4_ + tid];
                float4 h2 = hb[(size_t)(t + 2) * D4_ + tid];
                float4 h3 = hb[(size_t)(t + 3) * D4_ + tid];
                float4 h4 = hb[(size_t)(t + 4) * D4_ + tid];
                float4 h5 = hb[(size_t)(t + 5) * D4_ + tid];
                float4 h6 = hb[(size_t)(t + 6) * D4_ + tid];
                float4 h7 = hb[(size_t)(t + 7) * D4_ + tid];
                a0.x += w0 * h0.x; a0.y += w0 * h0.y; a0.z += w0 * h0.z; a0.w += w0 * h0.w;
                a1.x += w1 * h1.x; a1.y += w1 * h1.y; a1.z += w1 * h1.z; a1.w += w1 * h1.w;
                a2.x += w2 * h2.x; a2.y += w2 * h2.y; a2.z += w2 * h2.z; a2.w += w2 * h2.w;
                a3.x += w3 * h3.x; a3.y += w3 * h3.y; a3.z += w3 * h3.z; a3.w += w3 * h3.w;
                a0.x += w4 * h4.x; a0.y += w4 * h4.y; a0.z += w4 * h4.z; a0.w += w4 * h4.w;
                a1.x += w5 * h5.x; a1.y += w5 * h5.y; a1.z += w5 * h5.z; a1.w += w5 * h5.w;
                a2.x += w6 * h6.x; a2.y += w6 * h6.y; a2.z += w6 * h6.z; a2.w += w6 * h6.w;
                a3.x += w7 * h7.x; a3.y += w7 * h7.y; a3.z += w7 * h7.z; a3.w += w7 * h7.w;
            }
            for (; t + 4 <= j; t += 4) {
                float w0 = wgt[t], w1 = wgt[t + 1], w2 = wgt[t + 2], w3 = wgt[t + 3];
                float4 h0 = hb[(size_t)(t)     * D4_ + tid];
                float4 h1 = hb[(size_t)(t + 1) * D4_ + tid];
                float4 h2 = hb[(size_t)(t + 2) * D4_ + tid];
                float4 h3 = hb[(size_t)(t + 3) * D4_ + tid];
                a0.x += w0 * h0.x; a0.y += w0 * h0.y; a0.z += w0 * h0.z; a0.w += w0 * h0.w;
                a1.x += w1 * h1.x; a1.y += w1 * h1.y; a1.z += w1 * h1.z; a1.w += w1 * h1.w;
                a2.x += w2 * h2.x; a2.y += w2 * h2.y; a2.z += w2 * h2.z; a2.w += w2 * h2.w;
                a3.x += w3 * h3.x; a3.y += w3 * h3.y; a3.z += w3 * h3.z; a3.w += w3 * h3.w;
            }
            for (; t < j; t++) {
                float w0 = wgt[t];
                float4 h0 = hb[(size_t)t * D4_ + tid];
                a0.x += w0 * h0.x; a0.y += w0 * h0.y; a0.z += w0 * h0.z; a0.w += w0 * h0.w;
            }
            float rx = a0.x + a1.x + a2.x + a3.x;
            float ry = a0.y + a1.y + a2.y + a3.y;
            float rz = a0.z + a1.z + a2.z + a3.z;
            float rw = a0.w + a1.w + a2.w + a3.w;
            float* Hrow = out + ((size_t)(b * K_ + span)) * D_ + 4 * tid;
            atomicAdd(Hrow + 0, rx);
            atomicAdd(Hrow + 1, ry);
            atomicAdd(Hrow + 2, rz);
            atomicAdd(Hrow + 3, rw);
        }
        i = j;
    }
}

// ---------------------------------------------------------------------------
// Kernel 2: normalize out by denom, write sent_mask.
// grid (K_, B_), 192 threads: one block per (b,k) row.
// ---------------------------------------------------------------------------
__global__ __launch_bounds__(192)
void scale_kernel(float* __restrict__ out) {
    const int k = blockIdx.x;
    const int b = blockIdx.y;
    const int tid = threadIdx.x;
    const int bk = b * K_ + k;

    float d = g_denom[bk];
    float inv = (d > 0.0f) ? (1.0f / d) : 0.0f;

    float4* H4 = reinterpret_cast<float4*>(out + (size_t)bk * D_);
    float4 v = H4[tid];
    v.x *= inv; v.y *= inv; v.z *= inv; v.w *= inv;
    H4[tid] = v;

    if (tid == 0)
        out[(size_t)B_ * K_ * D_ + bk] = (d > 0.0f) ? 1.0f : 0.0f;
}

// ---------------------------------------------------------------------------
extern "C" void kernel_launch(void* const* d_in, const int* in_sizes, int n_in,
                              void* d_out, int out_size) {
    const float* token_hidden   = (const float*)d_in[0];
    const float* attention_mask = (const float*)d_in[1];
    const int*   span_starts    = (const int*)d_in[2];
    const int*   span_ends      = (const int*)d_in[3];
    const float* w_pool         = (const float*)d_in[4];
    const float* b_pool         = (const float*)d_in[5];
    float* out = (float*)d_out;

    zero_kernel<<<96, 256>>>(out);

    dim3 gridF(NCHUNK_, B_);
    fused_kernel<<<gridF, 192>>>(token_hidden, attention_mask,
                                 span_starts, span_ends,
                                 w_pool, b_pool, out);

    dim3 gridS(K_, B_);
    scale_kernel<<<gridS, 192>>>(out);
}